// round 2
// baseline (speedup 1.0000x reference)
#include <cuda_runtime.h>
#include <math.h>

#define Bsz  64
#define Lseq 200
#define NQc  1024
#define Dc   256
#define Hc   512
#define Qc   1024
#define BL   (Bsz*Lseq)     /* 12800 */
#define IN2D (2*Dc)         /* 512   */
#define G3H  (3*Hc)         /* 1536  */
#define NBLK 128

// ---------------- scratch (device globals; no allocation allowed) ------------
__device__ float g_X[BL*IN2D];       // [12800,512]  GRU input
__device__ float g_XG[BL*G3H];       // [12800,1536] input-transformed gates
__device__ float g_V[Qc*Hc];         // matrix @ fc_w
__device__ float g_ck[Qc];           // matrix @ fc_b
__device__ float g_gru[BL*Hc];       // all hidden states
__device__ float g_Hst[2][Bsz*Hc];   // double-buffered recurrent state
__device__ float g_mvals[BL];
__device__ float g_creg;
__device__ float g_mse;
__device__ float g_maskcnt;
__device__ unsigned g_barrier[256];

// ---------------- init: zero per-launch state (graph-replay safe) ------------
__global__ void init_k() {
    int tid = blockIdx.x*blockDim.x + threadIdx.x;
    if (tid < 256) g_barrier[tid] = 0u;
    if (tid == 0) { g_creg = 0.f; g_mse = 0.f; g_maskcnt = 0.f; }
    for (int i = tid; i < Bsz*Hc; i += gridDim.x*blockDim.x) g_Hst[0][i] = 0.f;
}

// ---------------- embeddings + c_reg ----------------------------------------
__global__ void __launch_bounds__(256) embed_k(
        const int* __restrict__ q_data, const int* __restrict__ qa_data,
        const int* __restrict__ pid_data,
        const float* __restrict__ q_emb, const float* __restrict__ qa_emb,
        const float* __restrict__ q_emb_diff, const float* __restrict__ qa_emb_diff,
        const float* __restrict__ diff_parm) {
    int m = blockIdx.x;
    int d = threadIdx.x;                       // 0..255 == D
    int q = q_data[m];
    int ans = (qa_data[m] - q) / NQc;          // {0,1}
    float pid = diff_parm[pid_data[m]];
    float qe = q_emb[q*Dc + d];
    float q2 = qe + pid * q_emb_diff[q*Dc + d];
    float qa2 = qa_emb[ans*Dc + d] + qe + pid * qa_emb_diff[ans*Dc + d];
    g_X[m*IN2D + d]      = qa2;                // concat order: [qa_embed2, q_embed2]
    g_X[m*IN2D + Dc + d] = q2;
    if (d == 0) atomicAdd(&g_creg, pid*pid*1e-5f);
}

// ---------------- fp32 SGEMM: C[M,N] = A[M,K] * B(+bias) --------------------
// TRANSB=1: B is [N,K] row-major (dot of rows).  TRANSB=0: B is [K,N].
template<int TRANSB>
__global__ void __launch_bounds__(256) sgemm_k(
        const float* __restrict__ A, const float* __restrict__ Bm,
        const float* __restrict__ bias, float* __restrict__ C,
        int M, int N, int K) {
    __shared__ float As[16][128];
    __shared__ float Bs[16][128];
    int tid = threadIdx.x;
    int bm = blockIdx.y * 128, bn = blockIdx.x * 128;
    int tr = (tid >> 4) * 8, tc = (tid & 15) * 8;
    float acc[8][8];
#pragma unroll
    for (int i = 0; i < 8; i++)
#pragma unroll
        for (int j = 0; j < 8; j++) acc[i][j] = 0.f;

    for (int k0 = 0; k0 < K; k0 += 16) {
#pragma unroll
        for (int p = 0; p < 2; p++) {
            int r = (tid >> 2) + p*64;
            int c = (tid & 3) * 4;
            float4 v = *(const float4*)&A[(size_t)(bm + r)*K + k0 + c];
            As[c+0][r] = v.x; As[c+1][r] = v.y; As[c+2][r] = v.z; As[c+3][r] = v.w;
        }
        if (TRANSB) {
#pragma unroll
            for (int p = 0; p < 2; p++) {
                int r = (tid >> 2) + p*64;
                int c = (tid & 3) * 4;
                float4 v = *(const float4*)&Bm[(size_t)(bn + r)*K + k0 + c];
                Bs[c+0][r] = v.x; Bs[c+1][r] = v.y; Bs[c+2][r] = v.z; Bs[c+3][r] = v.w;
            }
        } else {
#pragma unroll
            for (int p = 0; p < 2; p++) {
                int r = (tid >> 5) + p*8;
                int c = (tid & 31) * 4;
                *(float4*)&Bs[r][c] = *(const float4*)&Bm[(size_t)(k0 + r)*N + bn + c];
            }
        }
        __syncthreads();
#pragma unroll
        for (int k = 0; k < 16; k++) {
            float ra[8], rb[8];
            *(float4*)&ra[0] = *(const float4*)&As[k][tr];
            *(float4*)&ra[4] = *(const float4*)&As[k][tr+4];
            *(float4*)&rb[0] = *(const float4*)&Bs[k][tc];
            *(float4*)&rb[4] = *(const float4*)&Bs[k][tc+4];
#pragma unroll
            for (int i = 0; i < 8; i++)
#pragma unroll
                for (int j = 0; j < 8; j++) acc[i][j] += ra[i]*rb[j];
        }
        __syncthreads();
    }
    float bj[8];
#pragma unroll
    for (int j = 0; j < 8; j++) bj[j] = bias ? bias[bn + tc + j] : 0.f;
#pragma unroll
    for (int i = 0; i < 8; i++) {
#pragma unroll
        for (int j = 0; j < 8; j++) acc[i][j] += bj[j];
        *(float4*)&C[(size_t)(bm+tr+i)*N + bn + tc]     = *(float4*)&acc[i][0];
        *(float4*)&C[(size_t)(bm+tr+i)*N + bn + tc + 4] = *(float4*)&acc[i][4];
    }
}

// ---------------- ck[k] = matrix[k,:] . fc_b --------------------------------
__global__ void __launch_bounds__(256) ck_k(const float* __restrict__ matrix,
                                            const float* __restrict__ fc_b) {
    int warp = threadIdx.x >> 5, lane = threadIdx.x & 31;
    int k = blockIdx.x*8 + warp;
    float s = 0.f;
    for (int i = lane; i < Qc; i += 32) s += matrix[(size_t)k*Qc + i]*fc_b[i];
    for (int o = 16; o; o >>= 1) s += __shfl_down_sync(~0u, s, o);
    if (lane == 0) g_ck[k] = s;
}

// ---------------- persistent GRU recurrence (custom grid barrier) -----------
// 128 blocks (1/SM, all co-resident), each owns 4 h-dims for ALL 64 batches;
// its 12 w_hh rows (24KB) persist in SMEM the whole kernel; h staged per step.
__global__ void __launch_bounds__(256) gru_recur_k(
        const float* __restrict__ w_hh, const float* __restrict__ b_hh,
        const float* __restrict__ xg, float* __restrict__ gru_out) {
    extern __shared__ float sm[];
    float* Ws = sm;                  // [12][512]  rows: r j0..3, z j0..3, n j0..3
    float* Hs = sm + 12*512;         // [64][513] (pad 1 -> conflict-free scalar LDS)
    int tid = threadIdx.x;
    int j0 = blockIdx.x * 4;

    for (int idx = tid; idx < 12*512; idx += 256) {
        int row = idx >> 9, k = idx & 511;
        int gate = row >> 2, j = row & 3;
        Ws[idx] = w_hh[(size_t)(gate*Hc + j0 + j)*Hc + k];
    }
    int j = tid >> 6;                // 0..3
    int b = tid & 63;                // batch
    float bhr = b_hh[j0+j], bhz = b_hh[Hc + j0+j], bhn = b_hh[2*Hc + j0+j];
    const float* wr = Ws + j*512;
    const float* wz = Ws + (4+j)*512;
    const float* wn = Ws + (8+j)*512;

    for (int t = 0; t < Lseq; t++) {
        const float* Hg = g_Hst[t & 1];
        for (int idx = tid; idx < Bsz*Hc; idx += 256)
            Hs[(idx >> 9)*513 + (idx & 511)] = __ldcg(&Hg[idx]);
        __syncthreads();

        float ar = 0.f, az = 0.f, an = 0.f;
        const float* hrow = Hs + b*513;
#pragma unroll 8
        for (int k = 0; k < 512; k += 4) {
            float4 w4r = *(const float4*)&wr[k];
            float4 w4z = *(const float4*)&wz[k];
            float4 w4n = *(const float4*)&wn[k];
            float h0 = hrow[k], h1 = hrow[k+1], h2 = hrow[k+2], h3 = hrow[k+3];
            ar += w4r.x*h0; az += w4z.x*h0; an += w4n.x*h0;
            ar += w4r.y*h1; az += w4z.y*h1; an += w4n.y*h1;
            ar += w4r.z*h2; az += w4z.z*h2; an += w4n.z*h2;
            ar += w4r.w*h3; az += w4z.w*h3; an += w4n.w*h3;
        }
        size_t base = (size_t)(b*Lseq + t)*G3H + j0 + j;
        float xr  = xg[base];
        float xzv = xg[base + Hc];
        float xnv = xg[base + 2*Hc];
        float r = 1.f/(1.f + expf(-(xr  + ar + bhr)));
        float z = 1.f/(1.f + expf(-(xzv + az + bhz)));
        float n = tanhf(xnv + r*(an + bhn));
        float hold = hrow[j0 + j];
        float hnew = (1.f - z)*n + z*hold;
        gru_out[(size_t)(b*Lseq + t)*Hc + j0 + j] = hnew;
        g_Hst[(t+1) & 1][b*Hc + j0 + j] = hnew;
        __threadfence();
        __syncthreads();
        if (t < Lseq - 1) {
            if (tid == 0) {
                atomicAdd(&g_barrier[t], 1u);
                while (((volatile unsigned*)g_barrier)[t] < (unsigned)NBLK) { }
            }
            __syncthreads();
            __threadfence();
        }
    }
}

// ---------------- got[b,t] = h . V[q-1] + ck[q-1]; threshold -> mvals -------
__global__ void __launch_bounds__(256) got_k(const int* __restrict__ q_data) {
    int warp = threadIdx.x >> 5, lane = threadIdx.x & 31;
    int m = blockIdx.x*8 + warp;
    int qid = q_data[m] - 1;
    const float* h = g_gru + (size_t)m*Hc;
    const float* v = g_V   + (size_t)qid*Hc;
    float s = 0.f;
    for (int i = lane; i < Hc; i += 32) s += h[i]*v[i];
    for (int o = 16; o; o >>= 1) s += __shfl_down_sync(~0u, s, o);
    if (lane == 0) {
        float got = s + g_ck[qid];
        g_mvals[m] = (got >= 0.4f) ? 1.0f : got;
    }
}

// ---------------- per-batch stats + sequential DINA scan + outputs ----------
__global__ void __launch_bounds__(256) stats_k(
        const int* __restrict__ q_data, const int* __restrict__ qa_data,
        const float* __restrict__ target, float* __restrict__ out) {
    __shared__ int   q_s[Lseq];
    __shared__ int   qa_s[Lseq];
    __shared__ float mv_s[Lseq];
    __shared__ float mc_s[Lseq], mi_s[Lseq], nmc_s[Lseq], aa_s[Lseq];
    __shared__ float p_s[Lseq];
    __shared__ float guess[Qc], slip[Qc];
    int b = blockIdx.x, tid = threadIdx.x;

    for (int t = tid; t < Lseq; t += 256) {
        int qi = q_data[b*Lseq + t];
        q_s[t]  = qi - 1;
        qa_s[t] = (qa_data[b*Lseq + t] - qi) / NQc;
        mv_s[t] = g_mvals[b*Lseq + t];
    }
    for (int i = tid; i < Qc; i += 256) { guess[i] = 0.f; slip[i] = 0.f; }
    __syncthreads();

    for (int t = tid; t < Lseq; t += 256) {
        int qt = q_s[t];
        float mc = 0.f, mi = 0.f, nmc = 0.f; int aa = 0;
        for (int k = 0; k <= t; k++) {
            if (q_s[k] == qt) {
                aa++;
                if (k < t) {
                    float mv = mv_s[k];
                    bool mast = (mv == 1.0f);
                    bool notm = (mv == 0.0f);
                    if (qa_s[k] == 1) { if (mast) mc += 1.f; }
                    else              { if (mast) mi += 1.f; if (notm) nmc += 1.f; }
                }
            }
        }
        mc_s[t] = mc; mi_s[t] = mi; nmc_s[t] = nmc; aa_s[t] = (float)aa;
    }
    __syncthreads();

    if (tid == 0) {
        for (int t = 0; t < Lseq; t++) {
            int i = q_s[t];
            float m = mv_s[t];
            int qa = qa_s[t];
            float aaf = aa_s[t];
            bool m1 = (m == 1.0f);
            float g_upd = m1 ? (mc_s[t]/aaf)
                             : (qa == 0 ? 1.f - nmc_s[t]/aaf : nmc_s[t]/aaf);
            bool upd = m1 && (qa == 0);
            float new_g = upd ? guess[i] : g_upd;
            float new_s = upd ? (mi_s[t]/aaf) : slip[i];
            guess[i] = new_g; slip[i] = new_s;
            p_s[t] = (1.f - new_s)*(m*new_g + (1.f - new_s)*(1.f - m));
        }
    }
    __syncthreads();

    float lmse = 0.f, lcnt = 0.f;
    for (int t = tid; t < Lseq; t += 256) {
        float p = p_s[t];
        out[1 + b*Lseq + t] = 1.f/(1.f + expf(-p));
        float lab = target[b*Lseq + t];
        if (lab > -0.9f) { float d = p - lab; lmse += d*d; lcnt += 1.f; }
    }
    for (int o = 16; o; o >>= 1) {
        lmse += __shfl_down_sync(~0u, lmse, o);
        lcnt += __shfl_down_sync(~0u, lcnt, o);
    }
    if ((tid & 31) == 0 && (lmse != 0.f || lcnt != 0.f)) {
        atomicAdd(&g_mse, lmse);
        atomicAdd(&g_maskcnt, lcnt);
    }
}

__global__ void fin_k(float* out) {
    out[0]      = g_mse + g_creg;
    out[BL + 1] = g_maskcnt;
}

// ---------------- launch -----------------------------------------------------
extern "C" void kernel_launch(void* const* d_in, const int* in_sizes, int n_in,
                              void* d_out, int out_size) {
    const int*   q_data      = (const int*)  d_in[0];
    const int*   qa_data     = (const int*)  d_in[1];
    const int*   pid_data    = (const int*)  d_in[2];
    const float* matrix      = (const float*)d_in[3];
    const float* target      = (const float*)d_in[4];
    const float* q_emb       = (const float*)d_in[5];
    const float* qa_emb      = (const float*)d_in[6];
    const float* q_emb_diff  = (const float*)d_in[7];
    const float* qa_emb_diff = (const float*)d_in[8];
    const float* diff_parm   = (const float*)d_in[9];
    const float* w_ih        = (const float*)d_in[10];
    const float* w_hh        = (const float*)d_in[11];
    const float* b_ih        = (const float*)d_in[12];
    const float* b_hh        = (const float*)d_in[13];
    const float* fc_w        = (const float*)d_in[14];
    const float* fc_b        = (const float*)d_in[15];
    float* out = (float*)d_out;

    void *pX, *pXG, *pV, *pGRU;
    cudaGetSymbolAddress(&pX,  g_X);
    cudaGetSymbolAddress(&pXG, g_XG);
    cudaGetSymbolAddress(&pV,  g_V);
    cudaGetSymbolAddress(&pGRU, g_gru);

    const int recur_smem = (12*512 + 64*513) * (int)sizeof(float);
    cudaFuncSetAttribute(gru_recur_k,
                         cudaFuncAttributeMaxDynamicSharedMemorySize, recur_smem);

    init_k<<<32, 256>>>();
    embed_k<<<BL, 256>>>(q_data, qa_data, pid_data,
                         q_emb, qa_emb, q_emb_diff, qa_emb_diff, diff_parm);
    // XG = X @ w_ih^T + b_ih    [12800,1536]
    sgemm_k<1><<<dim3(G3H/128, BL/128), 256>>>((const float*)pX, w_ih, b_ih,
                                               (float*)pXG, BL, G3H, IN2D);
    // V = matrix @ fc_w         [1024,512]
    sgemm_k<0><<<dim3(Hc/128, Qc/128), 256>>>(matrix, fc_w, nullptr,
                                              (float*)pV, Qc, Hc, Qc);
    ck_k<<<Qc/8, 256>>>(matrix, fc_b);
    gru_recur_k<<<NBLK, 256, recur_smem>>>(w_hh, b_hh,
                                           (const float*)pXG, (float*)pGRU);
    got_k<<<BL/8, 256>>>(q_data);
    stats_k<<<Bsz, 256>>>(q_data, qa_data, target, out);
    fin_k<<<1, 1>>>(out);
}

// round 6
// speedup vs baseline: 1.4255x; 1.4255x over previous
#include <cuda_runtime.h>
#include <math.h>

#define Bsz  64
#define Lseq 200
#define NQc  1024
#define Dc   256
#define Hc   512
#define Qc   1024
#define BL   (Bsz*Lseq)     /* 12800 */
#define IN2D (2*Dc)         /* 512   */
#define G3H  (3*Hc)         /* 1536  */
#define NBLK 128

typedef unsigned long long ull;

// ---------------- packed f32x2 helpers (SASS FFMA2 via PTX) ------------------
__device__ __forceinline__ ull pack_dup(float x) {
    ull r; asm("mov.b64 %0, {%1, %1};" : "=l"(r) : "f"(x)); return r;
}
__device__ __forceinline__ void fma2(ull& d, ull a, ull b) {
    asm("fma.rn.f32x2 %0, %1, %2, %0;" : "+l"(d) : "l"(a), "l"(b));
}
__device__ __forceinline__ float2 unpack2(ull v) {
    float2 f; asm("mov.b64 {%0, %1}, %2;" : "=f"(f.x), "=f"(f.y) : "l"(v)); return f;
}

// ---------------- scratch (device globals; no allocation allowed) ------------
__device__ float g_X[BL*IN2D];       // [12800,512]  GRU input
__device__ float g_XG[BL*G3H];       // [12800,1536] input-transformed gates
__device__ float g_V[Qc*Hc];         // matrix @ fc_w
__device__ float g_ck[Qc];           // matrix @ fc_b
__device__ float g_gru[BL*Hc];       // all hidden states
__device__ float g_Hst[2][Bsz*Hc];   // double-buffered recurrent state
__device__ float g_mvals[BL];
__device__ float g_creg;
__device__ float g_mse;
__device__ float g_maskcnt;
__device__ unsigned g_barrier[256];

// ---------------- init: zero per-launch state (graph-replay safe) ------------
__global__ void init_k() {
    int tid = blockIdx.x*blockDim.x + threadIdx.x;
    if (tid < 256) g_barrier[tid] = 0u;
    if (tid == 0) { g_creg = 0.f; g_mse = 0.f; g_maskcnt = 0.f; }
    for (int i = tid; i < Bsz*Hc; i += gridDim.x*blockDim.x) g_Hst[0][i] = 0.f;
}

// ---------------- embeddings + c_reg ----------------------------------------
__global__ void __launch_bounds__(256) embed_k(
        const int* __restrict__ q_data, const int* __restrict__ qa_data,
        const int* __restrict__ pid_data,
        const float* __restrict__ q_emb, const float* __restrict__ qa_emb,
        const float* __restrict__ q_emb_diff, const float* __restrict__ qa_emb_diff,
        const float* __restrict__ diff_parm) {
    int m = blockIdx.x;
    int d = threadIdx.x;                       // 0..255 == D
    int q = q_data[m];
    int ans = (qa_data[m] - q) / NQc;          // {0,1}
    float pid = diff_parm[pid_data[m]];
    float qe = q_emb[q*Dc + d];
    float q2 = qe + pid * q_emb_diff[q*Dc + d];
    float qa2 = qa_emb[ans*Dc + d] + qe + pid * qa_emb_diff[ans*Dc + d];
    g_X[m*IN2D + d]      = qa2;                // concat order: [qa_embed2, q_embed2]
    g_X[m*IN2D + Dc + d] = q2;
    if (d == 0) atomicAdd(&g_creg, pid*pid*1e-5f);
}

// ---------------- fp32x2 SGEMM 128x128: C[M,N] = A[M,K] * B^T(+bias) --------
// B is [N,K] row-major (dot of rows). Uses packed FFMA2.
__global__ void __launch_bounds__(256) sgemm128_k(
        const float* __restrict__ A, const float* __restrict__ Bm,
        const float* __restrict__ bias, float* __restrict__ C,
        int M, int N, int K) {
    __shared__ float As[16][128];
    __shared__ float Bs[16][128];
    int tid = threadIdx.x;
    int bm = blockIdx.y * 128, bn = blockIdx.x * 128;
    int tr = (tid >> 4) * 8, tc = (tid & 15) * 8;
    ull acc2[8][4];
#pragma unroll
    for (int i = 0; i < 8; i++)
#pragma unroll
        for (int j = 0; j < 4; j++) acc2[i][j] = 0ull;

    for (int k0 = 0; k0 < K; k0 += 16) {
#pragma unroll
        for (int p = 0; p < 2; p++) {
            int r = (tid >> 2) + p*64;
            int c = (tid & 3) * 4;
            float4 v = *(const float4*)&A[(size_t)(bm + r)*K + k0 + c];
            As[c+0][r] = v.x; As[c+1][r] = v.y; As[c+2][r] = v.z; As[c+3][r] = v.w;
        }
#pragma unroll
        for (int p = 0; p < 2; p++) {
            int r = (tid >> 2) + p*64;
            int c = (tid & 3) * 4;
            float4 v = *(const float4*)&Bm[(size_t)(bn + r)*K + k0 + c];
            Bs[c+0][r] = v.x; Bs[c+1][r] = v.y; Bs[c+2][r] = v.z; Bs[c+3][r] = v.w;
        }
        __syncthreads();
#pragma unroll
        for (int k = 0; k < 16; k++) {
            float ra[8];
            *(float4*)&ra[0] = *(const float4*)&As[k][tr];
            *(float4*)&ra[4] = *(const float4*)&As[k][tr+4];
            ulonglong2 p0 = *(const ulonglong2*)&Bs[k][tc];     // pairs (tc,tc+1),(tc+2,tc+3)
            ulonglong2 p1 = *(const ulonglong2*)&Bs[k][tc+4];
#pragma unroll
            for (int i = 0; i < 8; i++) {
                ull a2 = pack_dup(ra[i]);
                fma2(acc2[i][0], a2, p0.x);
                fma2(acc2[i][1], a2, p0.y);
                fma2(acc2[i][2], a2, p1.x);
                fma2(acc2[i][3], a2, p1.y);
            }
        }
        __syncthreads();
    }
    float bj[8];
#pragma unroll
    for (int j = 0; j < 8; j++) bj[j] = bias ? bias[bn + tc + j] : 0.f;
#pragma unroll
    for (int i = 0; i < 8; i++) {
        float2 v0 = unpack2(acc2[i][0]);
        float2 v1 = unpack2(acc2[i][1]);
        float2 v2 = unpack2(acc2[i][2]);
        float2 v3 = unpack2(acc2[i][3]);
        float4 o0 = make_float4(v0.x+bj[0], v0.y+bj[1], v1.x+bj[2], v1.y+bj[3]);
        float4 o1 = make_float4(v2.x+bj[4], v2.y+bj[5], v3.x+bj[6], v3.y+bj[7]);
        *(float4*)&C[(size_t)(bm+tr+i)*N + bn + tc]     = o0;
        *(float4*)&C[(size_t)(bm+tr+i)*N + bn + tc + 4] = o1;
    }
}

// ---------------- SGEMM 64x64 (B is [K,N]): for V = matrix @ fc_w -----------
__global__ void __launch_bounds__(256) sgemm64_k(
        const float* __restrict__ A, const float* __restrict__ Bm,
        float* __restrict__ C, int M, int N, int K) {
    __shared__ float As[16][64];
    __shared__ float Bs[16][68];
    int tid = threadIdx.x;
    int bm = blockIdx.y * 64, bn = blockIdx.x * 64;
    int tr = (tid >> 4) * 4, tc = (tid & 15) * 4;
    float acc[4][4];
#pragma unroll
    for (int i = 0; i < 4; i++)
#pragma unroll
        for (int j = 0; j < 4; j++) acc[i][j] = 0.f;

    for (int k0 = 0; k0 < K; k0 += 16) {
        {
            int r = tid >> 2;             // 0..63
            int c = (tid & 3) * 4;
            float4 v = *(const float4*)&A[(size_t)(bm + r)*K + k0 + c];
            As[c+0][r] = v.x; As[c+1][r] = v.y; As[c+2][r] = v.z; As[c+3][r] = v.w;
        }
        {
            int r = tid >> 4;             // 0..15
            int c = (tid & 15) * 4;
            float4 v = *(const float4*)&Bm[(size_t)(k0 + r)*N + bn + c];
            Bs[r][c+0] = v.x; Bs[r][c+1] = v.y; Bs[r][c+2] = v.z; Bs[r][c+3] = v.w;
        }
        __syncthreads();
#pragma unroll
        for (int k = 0; k < 16; k++) {
            float ra[4], rb[4];
            *(float4*)&ra[0] = *(const float4*)&As[k][tr];
            rb[0] = Bs[k][tc]; rb[1] = Bs[k][tc+1]; rb[2] = Bs[k][tc+2]; rb[3] = Bs[k][tc+3];
#pragma unroll
            for (int i = 0; i < 4; i++)
#pragma unroll
                for (int j = 0; j < 4; j++) acc[i][j] += ra[i]*rb[j];
        }
        __syncthreads();
    }
#pragma unroll
    for (int i = 0; i < 4; i++)
        *(float4*)&C[(size_t)(bm+tr+i)*N + bn + tc] = *(float4*)&acc[i][0];
}

// ---------------- ck[k] = matrix[k,:] . fc_b --------------------------------
__global__ void __launch_bounds__(256) ck_k(const float* __restrict__ matrix,
                                            const float* __restrict__ fc_b) {
    int warp = threadIdx.x >> 5, lane = threadIdx.x & 31;
    int k = blockIdx.x*8 + warp;
    float s = 0.f;
    for (int i = lane; i < Qc; i += 32) s += matrix[(size_t)k*Qc + i]*fc_b[i];
    for (int o = 16; o; o >>= 1) s += __shfl_down_sync(~0u, s, o);
    if (lane == 0) g_ck[k] = s;
}

// ---------------- persistent GRU recurrence (custom grid barrier) -----------
// 128 blocks = 32 dim-groups(16 dims) x 4 batch-groups(16 batches).
// Weights (48 rows x 512 = 96KB) persist in SMEM; only 16 h-rows staged/step.
// Inner dot uses packed FFMA2 (fma.rn.f32x2).
#define DIMG 16
#define BATG 16
#define HPAD 516
__global__ void __launch_bounds__(256) gru_recur_k(
        const float* __restrict__ w_hh, const float* __restrict__ b_hh,
        const float* __restrict__ xg, float* __restrict__ gru_out) {
    extern __shared__ float sm[];
    float* Ws = sm;                       // [48][512] row = gate*16 + j
    float* Hs = sm + 48*512;              // [16][516] (16B-aligned rows, conflict-free)
    int tid = threadIdx.x;
    int dg = blockIdx.x >> 2, bg = blockIdx.x & 3;
    int j0 = dg*DIMG, b0 = bg*BATG;

    for (int idx = tid; idx < 48*512; idx += 256) {
        int row = idx >> 9, k = idx & 511;
        int gate = row >> 4, j = row & 15;
        Ws[idx] = w_hh[(size_t)(gate*Hc + j0 + j)*Hc + k];
    }
    int j  = tid >> 4;                    // 0..15 dim within group
    int bl = tid & 15;                    // 0..15 local batch
    int b  = b0 + bl;
    float bhr = b_hh[j0+j], bhz = b_hh[Hc + j0+j], bhn = b_hh[2*Hc + j0+j];
    const float* wr = Ws + j*512;
    const float* wz = Ws + (16+j)*512;
    const float* wn = Ws + (32+j)*512;

    for (int t = 0; t < Lseq; t++) {
        const float* Hg = g_Hst[t & 1] + (size_t)b0*Hc;
        for (int i4 = tid; i4 < BATG*Hc/4; i4 += 256) {
            int row = i4 >> 7, c4 = i4 & 127;
            *(float4*)&Hs[row*HPAD + c4*4] = __ldcg((const float4*)&Hg[(size_t)row*Hc + c4*4]);
        }
        __syncthreads();

        ull ra2 = 0, rb2 = 0, za2 = 0, zb2 = 0, na2 = 0, nb2 = 0;
        const float* hrow = Hs + bl*HPAD;
#pragma unroll 8
        for (int k = 0; k < 512; k += 4) {
            ulonglong2 h2  = *(const ulonglong2*)&hrow[k];
            ulonglong2 w2r = *(const ulonglong2*)&wr[k];
            ulonglong2 w2z = *(const ulonglong2*)&wz[k];
            ulonglong2 w2n = *(const ulonglong2*)&wn[k];
            fma2(ra2, w2r.x, h2.x); fma2(rb2, w2r.y, h2.y);
            fma2(za2, w2z.x, h2.x); fma2(zb2, w2z.y, h2.y);
            fma2(na2, w2n.x, h2.x); fma2(nb2, w2n.y, h2.y);
        }
        float2 fr0 = unpack2(ra2), fr1 = unpack2(rb2);
        float2 fz0 = unpack2(za2), fz1 = unpack2(zb2);
        float2 fn0 = unpack2(na2), fn1 = unpack2(nb2);
        float ar = (fr0.x + fr0.y) + (fr1.x + fr1.y);
        float az = (fz0.x + fz0.y) + (fz1.x + fz1.y);
        float an = (fn0.x + fn0.y) + (fn1.x + fn1.y);

        size_t base = (size_t)(b*Lseq + t)*G3H + j0 + j;
        float xr  = xg[base];
        float xzv = xg[base + Hc];
        float xnv = xg[base + 2*Hc];
        float r = 1.f/(1.f + expf(-(xr  + ar + bhr)));
        float z = 1.f/(1.f + expf(-(xzv + az + bhz)));
        float n = tanhf(xnv + r*(an + bhn));
        float hold = hrow[j0 + j];
        float hnew = (1.f - z)*n + z*hold;
        gru_out[(size_t)(b*Lseq + t)*Hc + j0 + j] = hnew;
        g_Hst[(t+1) & 1][b*Hc + j0 + j] = hnew;
        __threadfence();
        __syncthreads();
        if (t < Lseq - 1) {
            if (tid == 0) {
                atomicAdd(&g_barrier[t], 1u);
                while (((volatile unsigned*)g_barrier)[t] < (unsigned)NBLK) { }
            }
            __syncthreads();
            __threadfence();
        }
    }
}

// ---------------- got[b,t] = h . V[q-1] + ck[q-1]; threshold -> mvals -------
__global__ void __launch_bounds__(256) got_k(const int* __restrict__ q_data) {
    int warp = threadIdx.x >> 5, lane = threadIdx.x & 31;
    int m = blockIdx.x*8 + warp;
    int qid = q_data[m] - 1;
    const float* h = g_gru + (size_t)m*Hc;
    const float* v = g_V   + (size_t)qid*Hc;
    float s = 0.f;
    for (int i = lane; i < Hc; i += 32) s += h[i]*v[i];
    for (int o = 16; o; o >>= 1) s += __shfl_down_sync(~0u, s, o);
    if (lane == 0) {
        float got = s + g_ck[qid];
        g_mvals[m] = (got >= 0.4f) ? 1.0f : got;
    }
}

// ---------------- per-batch stats + sequential DINA scan + outputs ----------
__global__ void __launch_bounds__(256) stats_k(
        const int* __restrict__ q_data, const int* __restrict__ qa_data,
        const float* __restrict__ target, float* __restrict__ out) {
    __shared__ int   q_s[Lseq];
    __shared__ int   qa_s[Lseq];
    __shared__ float mv_s[Lseq];
    __shared__ float mc_s[Lseq], mi_s[Lseq], nmc_s[Lseq], aa_s[Lseq];
    __shared__ float p_s[Lseq];
    __shared__ float guess[Qc], slip[Qc];
    int b = blockIdx.x, tid = threadIdx.x;

    for (int t = tid; t < Lseq; t += 256) {
        int qi = q_data[b*Lseq + t];
        q_s[t]  = qi - 1;
        qa_s[t] = (qa_data[b*Lseq + t] - qi) / NQc;
        mv_s[t] = g_mvals[b*Lseq + t];
    }
    for (int i = tid; i < Qc; i += 256) { guess[i] = 0.f; slip[i] = 0.f; }
    __syncthreads();

    for (int t = tid; t < Lseq; t += 256) {
        int qt = q_s[t];
        float mc = 0.f, mi = 0.f, nmc = 0.f; int aa = 0;
        for (int k = 0; k <= t; k++) {
            if (q_s[k] == qt) {
                aa++;
                if (k < t) {
                    float mv = mv_s[k];
                    bool mast = (mv == 1.0f);
                    bool notm = (mv == 0.0f);
                    if (qa_s[k] == 1) { if (mast) mc += 1.f; }
                    else              { if (mast) mi += 1.f; if (notm) nmc += 1.f; }
                }
            }
        }
        mc_s[t] = mc; mi_s[t] = mi; nmc_s[t] = nmc; aa_s[t] = (float)aa;
    }
    __syncthreads();

    if (tid == 0) {
        for (int t = 0; t < Lseq; t++) {
            int i = q_s[t];
            float m = mv_s[t];
            int qa = qa_s[t];
            float aaf = aa_s[t];
            bool m1 = (m == 1.0f);
            float g_upd = m1 ? (mc_s[t]/aaf)
                             : (qa == 0 ? 1.f - nmc_s[t]/aaf : nmc_s[t]/aaf);
            bool upd = m1 && (qa == 0);
            float new_g = upd ? guess[i] : g_upd;
            float new_s = upd ? (mi_s[t]/aaf) : slip[i];
            guess[i] = new_g; slip[i] = new_s;
            p_s[t] = (1.f - new_s)*(m*new_g + (1.f - new_s)*(1.f - m));
        }
    }
    __syncthreads();

    float lmse = 0.f, lcnt = 0.f;
    for (int t = tid; t < Lseq; t += 256) {
        float p = p_s[t];
        out[1 + b*Lseq + t] = 1.f/(1.f + expf(-p));
        float lab = target[b*Lseq + t];
        if (lab > -0.9f) { float d = p - lab; lmse += d*d; lcnt += 1.f; }
    }
    for (int o = 16; o; o >>= 1) {
        lmse += __shfl_down_sync(~0u, lmse, o);
        lcnt += __shfl_down_sync(~0u, lcnt, o);
    }
    if ((tid & 31) == 0 && (lmse != 0.f || lcnt != 0.f)) {
        atomicAdd(&g_mse, lmse);
        atomicAdd(&g_maskcnt, lcnt);
    }
}

__global__ void fin_k(float* out) {
    out[0]      = g_mse + g_creg;
    out[BL + 1] = g_maskcnt;
}

// ---------------- launch -----------------------------------------------------
extern "C" void kernel_launch(void* const* d_in, const int* in_sizes, int n_in,
                              void* d_out, int out_size) {
    const int*   q_data      = (const int*)  d_in[0];
    const int*   qa_data     = (const int*)  d_in[1];
    const int*   pid_data    = (const int*)  d_in[2];
    const float* matrix      = (const float*)d_in[3];
    const float* target      = (const float*)d_in[4];
    const float* q_emb       = (const float*)d_in[5];
    const float* qa_emb      = (const float*)d_in[6];
    const float* q_emb_diff  = (const float*)d_in[7];
    const float* qa_emb_diff = (const float*)d_in[8];
    const float* diff_parm   = (const float*)d_in[9];
    const float* w_ih        = (const float*)d_in[10];
    const float* w_hh        = (const float*)d_in[11];
    const float* b_ih        = (const float*)d_in[12];
    const float* b_hh        = (const float*)d_in[13];
    const float* fc_w        = (const float*)d_in[14];
    const float* fc_b        = (const float*)d_in[15];
    float* out = (float*)d_out;

    void *pX, *pXG, *pV, *pGRU;
    cudaGetSymbolAddress(&pX,  g_X);
    cudaGetSymbolAddress(&pXG, g_XG);
    cudaGetSymbolAddress(&pV,  g_V);
    cudaGetSymbolAddress(&pGRU, g_gru);

    const int recur_smem = (48*512 + BATG*HPAD) * (int)sizeof(float);
    cudaFuncSetAttribute(gru_recur_k,
                         cudaFuncAttributeMaxDynamicSharedMemorySize, recur_smem);

    init_k<<<32, 256>>>();
    embed_k<<<BL, 256>>>(q_data, qa_data, pid_data,
                         q_emb, qa_emb, q_emb_diff, qa_emb_diff, diff_parm);
    // XG = X @ w_ih^T + b_ih    [12800,1536]
    sgemm128_k<<<dim3(G3H/128, BL/128), 256>>>((const float*)pX, w_ih, b_ih,
                                               (float*)pXG, BL, G3H, IN2D);
    // V = matrix @ fc_w         [1024,512]
    sgemm64_k<<<dim3(Hc/64, Qc/64), 256>>>(matrix, fc_w, (float*)pV, Qc, Hc, Qc);
    ck_k<<<Qc/8, 256>>>(matrix, fc_b);
    gru_recur_k<<<NBLK, 256, recur_smem>>>(w_hh, b_hh,
                                           (const float*)pXG, (float*)pGRU);
    got_k<<<BL/8, 256>>>(q_data);
    stats_k<<<Bsz, 256>>>(q_data, qa_data, target, out);
    fin_k<<<1, 1>>>(out);
}